// round 1
// baseline (speedup 1.0000x reference)
#include <cuda_runtime.h>
#include <cuda_bf16.h>
#include <math.h>

// ---------------------------------------------------------------------------
// Problem constants
// ---------------------------------------------------------------------------
#define N_MP 2
#define B_SZ 1024
#define S_FAN 10
#define D_DIM 512
#define E_DIM 64
#define ATT_DIM 128
#define N_CLASSES 8
#define N_NODES 4096

#define N1_ROWS (B_SZ)            // 1024 rows, each S_FAN neighbors
#define N2_ROWS (B_SZ * S_FAN)    // 10240 rows

// ---------------------------------------------------------------------------
// Scratch arena (floats). All offsets multiple of 4 (16B aligned).
// ---------------------------------------------------------------------------
#define OFF_E0   0LL                              // 2 * 10240 * 64
#define SZ_E0    (2LL*10240*64)
#define OFF_G0   (OFF_E0 + SZ_E0)                 // 2 * 1024 * 10
#define SZ_G0    (2LL*1024*10)
#define OFF_G1   (OFF_G0 + SZ_G0)                 // 2 * 10240 * 10
#define SZ_G1    (2LL*10240*10)
#define OFF_G2   (OFF_G1 + SZ_G1)                 // 2 * 1024 * 10
#define SZ_G2    (2LL*1024*10)
#define OFF_X0   (OFF_G2 + SZ_G2)                 // 2 * 1024 * 1024
#define SZ_X0    (2LL*1024*1024)
#define OFF_X1   (OFF_X0 + SZ_X0)                 // 2 * 10240 * 1024
#define SZ_X1    (2LL*10240*1024)
#define OFF_H0   (OFF_X1 + SZ_X1)                 // 2 * 1024 * 512
#define SZ_H0    (2LL*1024*512)
#define OFF_H1   (OFF_H0 + SZ_H0)                 // 2 * 10240 * 512
#define SZ_H1    (2LL*10240*512)
#define OFF_EIN  (OFF_H1 + SZ_H1)                 // 2 * 10240 * 1088
#define SZ_EIN   (2LL*10240*1088)
#define OFF_NE0  (OFF_EIN + SZ_EIN)               // 2 * 10240 * 64
#define SZ_NE0   (2LL*10240*64)
#define OFF_X2   (OFF_NE0 + SZ_NE0)               // 2 * 1024 * 1024
#define SZ_X2    (2LL*1024*1024)
#define OFF_OUT  (OFF_X2 + SZ_X2)                 // 2 * 1024 * 512
#define SZ_OUT   (2LL*1024*512)
#define OFF_ATT  (OFF_OUT + SZ_OUT)               // 2 * 1024
#define SZ_ATT   (2048LL)
#define SCRATCH_TOTAL (OFF_ATT + SZ_ATT)

__device__ float g_scratch[SCRATCH_TOTAL];

// ---------------------------------------------------------------------------
// Edge gating: one warp per row. Computes scores[s] = edge_emb[eid]·v_gate,
// softmax over S, optionally stores the gathered edge rows.
// adjs != null : eid = adjs[src*4096 + nb]   (graph gather)
// adjs == null : eid = row*S + s             (contiguous, layer-1 gating)
// ---------------------------------------------------------------------------
__global__ void edge_gate_kernel(
    const int* __restrict__ src_ids, long long src_mp,
    const int* __restrict__ nb_ids,  long long nb_mp,
    const int* __restrict__ adjs,
    const float* __restrict__ edge_feat, long long ef_mp,
    const float* __restrict__ vg, long long vg_mp,
    float* __restrict__ gate_out, long long gate_mp,
    float* __restrict__ e_out, long long e_mp,
    int n_rows)
{
    int mp   = blockIdx.y;
    int warp = threadIdx.x >> 5;
    int lane = threadIdx.x & 31;
    int row  = blockIdx.x * (blockDim.x >> 5) + warp;
    if (row >= n_rows) return;

    const float* vgp = vg + (long long)mp * vg_mp;
    float v0 = vgp[lane], v1 = vgp[lane + 32];
    const float* ef = edge_feat + (long long)mp * ef_mp;

    int srcn = 0;
    if (adjs) srcn = src_ids[(long long)mp * src_mp + row];

    float scores[S_FAN];
#pragma unroll
    for (int s = 0; s < S_FAN; s++) {
        int eid;
        if (adjs) {
            int nb = nb_ids[(long long)mp * nb_mp + (long long)row * S_FAN + s];
            eid = adjs[(long long)srcn * N_NODES + nb];
        } else {
            eid = row * S_FAN + s;
        }
        const float* er = ef + (long long)eid * E_DIM;
        float e0 = er[lane], e1 = er[lane + 32];
        if (e_out) {
            float* eo = e_out + (long long)mp * e_mp + ((long long)row * S_FAN + s) * E_DIM;
            eo[lane] = e0; eo[lane + 32] = e1;
        }
        float p = e0 * v0 + e1 * v1;
#pragma unroll
        for (int off = 16; off; off >>= 1)
            p += __shfl_xor_sync(0xffffffffu, p, off);
        scores[s] = p;
    }
    // softmax over S (all lanes hold identical scores)
    float m = scores[0];
#pragma unroll
    for (int s = 1; s < S_FAN; s++) m = fmaxf(m, scores[s]);
    float sum = 0.f;
#pragma unroll
    for (int s = 0; s < S_FAN; s++) { scores[s] = expf(scores[s] - m); sum += scores[s]; }
    float inv = 1.f / sum;
    float* go = gate_out + (long long)mp * gate_mp + (long long)row * S_FAN;
#pragma unroll
    for (int s = 0; s < S_FAN; s++)
        if (lane == s) go[s] = scores[s] * inv;
}

// ---------------------------------------------------------------------------
// Gather rows of 512 floats (identity when ids==null). block = 128, float4.
// ---------------------------------------------------------------------------
__global__ void gather_rows_kernel(
    const int* __restrict__ ids, long long ids_mp,
    const float* __restrict__ src, long long src_mp, int src_row_stride,
    float* __restrict__ out, long long out_mp, int out_row_stride)
{
    int mp = blockIdx.y;
    int row = blockIdx.x;
    int r = ids ? ids[(long long)mp * ids_mp + row] : row;
    const float4* s = (const float4*)(src + (long long)mp * src_mp + (long long)r * src_row_stride);
    float4* o = (float4*)(out + (long long)mp * out_mp + (long long)row * out_row_stride);
    o[threadIdx.x] = s[threadIdx.x];
}

// ---------------------------------------------------------------------------
// Gate-weighted gather-sum over S neighbors, 512-dim rows. block = 128.
// nb == null : neighbor index = row*S + s (contiguous).
// ---------------------------------------------------------------------------
__global__ void weighted_gather_kernel(
    const int* __restrict__ nb, long long nb_mp,
    const float* __restrict__ gate, long long gate_mp,
    const float* __restrict__ src, long long src_mp,
    float* __restrict__ out, long long out_mp, int out_row_stride, int col_off)
{
    int mp = blockIdx.y;
    int row = blockIdx.x;
    int t = threadIdx.x;
    const float* srcp = src + (long long)mp * src_mp;
    const float* gp = gate + (long long)mp * gate_mp + (long long)row * S_FAN;
    float4 acc = make_float4(0.f, 0.f, 0.f, 0.f);
#pragma unroll
    for (int s = 0; s < S_FAN; s++) {
        float w = gp[s];
        int idx = nb ? nb[(long long)mp * nb_mp + (long long)row * S_FAN + s]
                     : row * S_FAN + s;
        float4 v = ((const float4*)(srcp + (long long)idx * D_DIM))[t];
        acc.x = fmaf(w, v.x, acc.x);
        acc.y = fmaf(w, v.y, acc.y);
        acc.z = fmaf(w, v.z, acc.z);
        acc.w = fmaf(w, v.w, acc.w);
    }
    ((float4*)(out + (long long)mp * out_mp + (long long)row * out_row_stride + col_off))[t] = acc;
}

// ---------------------------------------------------------------------------
// Concat edge-update input: EIN[i] = [H0[i/10] | H1[i] | E0[i]] (1088 floats)
// ---------------------------------------------------------------------------
__global__ void concat_ein_kernel(
    const float* __restrict__ H0, long long h0_mp,
    const float* __restrict__ H1, long long h1_mp,
    const float* __restrict__ E0, long long e0_mp,
    float* __restrict__ EIN, long long ein_mp)
{
    int mp = blockIdx.y;
    int row = blockIdx.x;
    const float4* h0 = (const float4*)(H0 + (long long)mp * h0_mp + (long long)(row / S_FAN) * D_DIM);
    const float4* h1 = (const float4*)(H1 + (long long)mp * h1_mp + (long long)row * D_DIM);
    const float4* e0 = (const float4*)(E0 + (long long)mp * e0_mp + (long long)row * E_DIM);
    float4* o = (float4*)(EIN + (long long)mp * ein_mp + (long long)row * (2 * D_DIM + E_DIM));
    for (int i = threadIdx.x; i < (2 * D_DIM + E_DIM) / 4; i += blockDim.x) {
        float4 v;
        if (i < 128)      v = h0[i];
        else if (i < 256) v = h1[i - 128];
        else              v = e0[i - 256];
        o[i] = v;
    }
}

// ---------------------------------------------------------------------------
// Tiled SGEMM with fused bias + ReLU.  C = relu(A[M,K] @ W[K,N] + bias)
// grid.z = metapath (separate operand strides).
// Requires M%BM==0, N%BN==0, K%BK==0, BK%4==0.
// ---------------------------------------------------------------------------
template<int BM, int BN, int BK, int TM, int TN>
__global__ __launch_bounds__((BM/TM)*(BN/TN))
void sgemm_bias_relu(
    const float* __restrict__ A, long long A_mp,
    const float* __restrict__ W, long long W_mp,
    const float* __restrict__ bias, long long b_mp,
    float* __restrict__ C, long long C_mp,
    int M, int N, int K)
{
    constexpr int TX = BN / TN;
    constexpr int TY = BM / TM;
    constexpr int THREADS = TX * TY;
    __shared__ float As[BK][BM + 4];
    __shared__ float Bs[BK][BN];

    int mp = blockIdx.z;
    const float* Ap = A + (long long)mp * A_mp + (long long)blockIdx.y * BM * K;
    const float* Wp = W + (long long)mp * W_mp + blockIdx.x * BN;
    int tid = threadIdx.x;
    int tx = tid % TX;
    int ty = tid / TX;

    float acc[TM][TN];
#pragma unroll
    for (int i = 0; i < TM; i++)
#pragma unroll
        for (int j = 0; j < TN; j++) acc[i][j] = 0.f;

    for (int k0 = 0; k0 < K; k0 += BK) {
        // load A tile (transposed into smem)
#pragma unroll
        for (int i = tid; i < BM * BK / 4; i += THREADS) {
            int r = i / (BK / 4);
            int c4 = (i % (BK / 4)) * 4;
            float4 v = *(const float4*)(Ap + (long long)r * K + k0 + c4);
            As[c4 + 0][r] = v.x;
            As[c4 + 1][r] = v.y;
            As[c4 + 2][r] = v.z;
            As[c4 + 3][r] = v.w;
        }
        // load W tile
#pragma unroll
        for (int i = tid; i < BK * BN / 4; i += THREADS) {
            int r = i / (BN / 4);
            int c4 = (i % (BN / 4)) * 4;
            *(float4*)(&Bs[r][c4]) = *(const float4*)(Wp + (long long)(k0 + r) * N + c4);
        }
        __syncthreads();
#pragma unroll
        for (int k = 0; k < BK; k++) {
            float ra[TM], rb[TN];
#pragma unroll
            for (int i = 0; i < TM; i++) ra[i] = As[k][ty * TM + i];
#pragma unroll
            for (int j = 0; j < TN; j++) rb[j] = Bs[k][tx * TN + j];
#pragma unroll
            for (int i = 0; i < TM; i++)
#pragma unroll
                for (int j = 0; j < TN; j++)
                    acc[i][j] = fmaf(ra[i], rb[j], acc[i][j]);
        }
        __syncthreads();
    }

    const float* bp = bias + (long long)mp * b_mp + blockIdx.x * BN;
    float* Cp = C + (long long)mp * C_mp + ((long long)blockIdx.y * BM) * N + blockIdx.x * BN;
#pragma unroll
    for (int i = 0; i < TM; i++) {
        int r = ty * TM + i;
#pragma unroll
        for (int j = 0; j < TN; j++) {
            int c = tx * TN + j;
            float v = acc[i][j] + bp[c];
            Cp[(long long)r * N + c] = fmaxf(v, 0.f);
        }
    }
}

// ---------------------------------------------------------------------------
// Metapath attention score: att[g] = tanh(OUT[g]@Wa + ba) · va
// grid = N_MP*B, block = 128 (= ATT_DIM)
// ---------------------------------------------------------------------------
__global__ void att_kernel(const float* __restrict__ OUT,
                           const float* __restrict__ Wa,
                           const float* __restrict__ ba,
                           const float* __restrict__ va,
                           float* __restrict__ att)
{
    __shared__ float srow[D_DIM];
    __shared__ float red[4];
    int g = blockIdx.x;
    const float4* o = (const float4*)(OUT + (long long)g * D_DIM);
    ((float4*)srow)[threadIdx.x] = o[threadIdx.x];
    __syncthreads();
    int j = threadIdx.x;
    float acc = ba[j];
#pragma unroll 8
    for (int k = 0; k < D_DIM; k++)
        acc = fmaf(srow[k], Wa[k * ATT_DIM + j], acc);
    float p = tanhf(acc) * va[j];
#pragma unroll
    for (int off = 16; off; off >>= 1)
        p += __shfl_xor_sync(0xffffffffu, p, off);
    if ((threadIdx.x & 31) == 0) red[threadIdx.x >> 5] = p;
    __syncthreads();
    if (threadIdx.x == 0) att[g] = red[0] + red[1] + red[2] + red[3];
}

// ---------------------------------------------------------------------------
// Final: softmax over metapaths, weighted sum, FC + ReLU. grid = B, block 128
// ---------------------------------------------------------------------------
__global__ void final_kernel(const float* __restrict__ OUT,
                             const float* __restrict__ att,
                             const float* __restrict__ W_fc,
                             const float* __restrict__ b_fc,
                             float* __restrict__ out)
{
    __shared__ float agg[D_DIM];
    int b = blockIdx.x;
    float a0 = att[b], a1 = att[B_SZ + b];
    float m = fmaxf(a0, a1);
    float e0 = expf(a0 - m), e1 = expf(a1 - m);
    float inv = 1.f / (e0 + e1);
    float w0 = e0 * inv, w1 = e1 * inv;
    const float4* o0 = (const float4*)(OUT + (long long)b * D_DIM);
    const float4* o1 = (const float4*)(OUT + (long long)(B_SZ + b) * D_DIM);
    float4 v0 = o0[threadIdx.x], v1 = o1[threadIdx.x];
    float4 r;
    r.x = w0 * v0.x + w1 * v1.x;
    r.y = w0 * v0.y + w1 * v1.y;
    r.z = w0 * v0.z + w1 * v1.z;
    r.w = w0 * v0.w + w1 * v1.w;
    ((float4*)agg)[threadIdx.x] = r;
    __syncthreads();
    int warp = threadIdx.x >> 5;
    int lane = threadIdx.x & 31;
    for (int c = warp; c < N_CLASSES; c += 4) {
        float s = 0.f;
        for (int k = lane; k < D_DIM; k += 32)
            s = fmaf(agg[k], W_fc[k * N_CLASSES + c], s);
#pragma unroll
        for (int off = 16; off; off >>= 1)
            s += __shfl_xor_sync(0xffffffffu, s, off);
        if (lane == 0) out[b * N_CLASSES + c] = fmaxf(s + b_fc[c], 0.f);
    }
}

// ---------------------------------------------------------------------------
// Launch
// ---------------------------------------------------------------------------
extern "C" void kernel_launch(void* const* d_in, const int* in_sizes, int n_in,
                              void* d_out, int out_size)
{
    const int*   ids      = (const int*)d_in[0];
    const float* feats    = (const float*)d_in[1];
    const int*   adjs     = (const int*)d_in[2];
    const float* edge_emb = (const float*)d_in[3];
    const int*   n1       = (const int*)d_in[4];
    const int*   n2       = (const int*)d_in[5];
    const float* W_agg    = (const float*)d_in[6];
    const float* b_agg    = (const float*)d_in[7];
    const float* v_gate   = (const float*)d_in[8];
    const float* W_edge   = (const float*)d_in[9];
    const float* b_edge   = (const float*)d_in[10];
    const float* Wa       = (const float*)d_in[11];
    const float* ba       = (const float*)d_in[12];
    const float* va       = (const float*)d_in[13];
    const float* W_fc     = (const float*)d_in[14];
    const float* b_fc     = (const float*)d_in[15];
    float* out = (float*)d_out;

    float* S;
    cudaGetSymbolAddress((void**)&S, g_scratch);
    float* E0  = S + OFF_E0;
    float* G0  = S + OFF_G0;
    float* G1  = S + OFF_G1;
    float* G2  = S + OFF_G2;
    float* X0  = S + OFF_X0;
    float* X1  = S + OFF_X1;
    float* H0  = S + OFF_H0;
    float* H1  = S + OFF_H1;
    float* EIN = S + OFF_EIN;
    float* NE0 = S + OFF_NE0;
    float* X2  = S + OFF_X2;
    float* OUTB= S + OFF_OUT;
    float* ATT = S + OFF_ATT;

    // per-mp strides
    const long long E0_MP  = 10240LL * 64;
    const long long G0_MP  = 1024LL * 10;
    const long long G1_MP  = 10240LL * 10;
    const long long G2_MP  = 1024LL * 10;
    const long long X0_MP  = 1024LL * 1024;
    const long long X1_MP  = 10240LL * 1024;
    const long long H0_MP  = 1024LL * 512;
    const long long H1_MP  = 10240LL * 512;
    const long long EIN_MP = 10240LL * 1088;
    const long long NE0_MP = 10240LL * 64;
    const long long X2_MP  = 1024LL * 1024;
    const long long OUT_MP = 1024LL * 512;
    const long long WAGG_MP = 2LL * 1024 * 512;   // [2,2,1024,512]
    const long long BAGG_MP = 2LL * 512;
    const long long VG_MP   = 2LL * 64;
    const long long WEDGE_MP = 2LL * 1088 * 64;
    const long long BEDGE_MP = 2LL * 64;

    // 1) hop-1 gating (and gather E0)
    edge_gate_kernel<<<dim3(N1_ROWS / 4, N_MP), 128>>>(
        ids, 0, n1, (long long)N1_ROWS * S_FAN, adjs,
        edge_emb, 0, v_gate, VG_MP, G0, G0_MP, E0, E0_MP, N1_ROWS);

    // 2) hop-2 gating (scores only)
    edge_gate_kernel<<<dim3(N2_ROWS / 4, N_MP), 128>>>(
        n1, (long long)N1_ROWS * S_FAN, n2, (long long)N2_ROWS * S_FAN, adjs,
        edge_emb, 0, v_gate, VG_MP, G1, G1_MP, nullptr, 0, N2_ROWS);

    // 3) X0 left = feats[ids]
    gather_rows_kernel<<<dim3(N1_ROWS, N_MP), 128>>>(
        ids, 0, feats, 0, D_DIM, X0, X0_MP, 2 * D_DIM);
    // 4) X0 right = gate-weighted sum of feats[neigh1]
    weighted_gather_kernel<<<dim3(N1_ROWS, N_MP), 128>>>(
        n1, (long long)N1_ROWS * S_FAN, G0, G0_MP, feats, 0,
        X0, X0_MP, 2 * D_DIM, D_DIM);
    // 5) X1 left = feats[neigh1]
    gather_rows_kernel<<<dim3(N2_ROWS, N_MP), 128>>>(
        n1, (long long)N1_ROWS * S_FAN, feats, 0, D_DIM, X1, X1_MP, 2 * D_DIM);
    // 6) X1 right = gate-weighted sum of feats[neigh2]
    weighted_gather_kernel<<<dim3(N2_ROWS, N_MP), 128>>>(
        n2, (long long)N2_ROWS * S_FAN, G1, G1_MP, feats, 0,
        X1, X1_MP, 2 * D_DIM, D_DIM);

    // 7) H0 = relu(X0 @ W_agg[mp,0] + b_agg[mp,0])   [1024,1024]x[1024,512]
    sgemm_bias_relu<128, 64, 8, 8, 4><<<dim3(D_DIM / 64, N1_ROWS / 128, N_MP), 256>>>(
        X0, X0_MP, W_agg, WAGG_MP, b_agg, BAGG_MP, H0, H0_MP,
        N1_ROWS, D_DIM, 2 * D_DIM);
    // 8) H1 = relu(X1 @ W_agg[mp,0] + b_agg[mp,0])   [10240,1024]x[1024,512]
    sgemm_bias_relu<128, 64, 8, 8, 4><<<dim3(D_DIM / 64, N2_ROWS / 128, N_MP), 256>>>(
        X1, X1_MP, W_agg, WAGG_MP, b_agg, BAGG_MP, H1, H1_MP,
        N2_ROWS, D_DIM, 2 * D_DIM);

    // 9) EIN = [H0 repeat | H1 | E0]
    concat_ein_kernel<<<dim3(N2_ROWS, N_MP), 128>>>(
        H0, H0_MP, H1, H1_MP, E0, E0_MP, EIN, EIN_MP);
    // 10) NE0 = relu(EIN @ W_edge[mp,0] + b_edge[mp,0])   [10240,1088]x[1088,64]
    sgemm_bias_relu<64, 64, 8, 4, 4><<<dim3(E_DIM / 64, N2_ROWS / 64, N_MP), 256>>>(
        EIN, EIN_MP, W_edge, WEDGE_MP, b_edge, BEDGE_MP, NE0, NE0_MP,
        N2_ROWS, E_DIM, 2 * D_DIM + E_DIM);

    // 11) layer-1 gating from NE0 (contiguous edges), v_gate[mp,1]
    edge_gate_kernel<<<dim3(N1_ROWS / 4, N_MP), 128>>>(
        nullptr, 0, nullptr, 0, nullptr,
        NE0, NE0_MP, v_gate + E_DIM, VG_MP, G2, G2_MP, nullptr, 0, N1_ROWS);

    // 12) X2 left = H0
    gather_rows_kernel<<<dim3(N1_ROWS, N_MP), 128>>>(
        nullptr, 0, H0, H0_MP, D_DIM, X2, X2_MP, 2 * D_DIM);
    // 13) X2 right = gate-weighted sum of H1 (contiguous neighbors)
    weighted_gather_kernel<<<dim3(N1_ROWS, N_MP), 128>>>(
        nullptr, 0, G2, G2_MP, H1, H1_MP, X2, X2_MP, 2 * D_DIM, D_DIM);

    // 14) OUT = relu(X2 @ W_agg[mp,1] + b_agg[mp,1])
    sgemm_bias_relu<128, 64, 8, 8, 4><<<dim3(D_DIM / 64, N1_ROWS / 128, N_MP), 256>>>(
        X2, X2_MP, W_agg + 1024LL * 512, WAGG_MP, b_agg + 512, BAGG_MP,
        OUTB, OUT_MP, N1_ROWS, D_DIM, 2 * D_DIM);

    // 15) metapath attention scores
    att_kernel<<<N_MP * B_SZ, ATT_DIM>>>(OUTB, Wa, ba, va, ATT);
    // 16) softmax over metapaths + weighted sum + FC + ReLU
    final_kernel<<<B_SZ, 128>>>(OUTB, ATT, W_fc, b_fc, out);
}

// round 3
// speedup vs baseline: 2.0940x; 2.0940x over previous
#include <cuda_runtime.h>
#include <cuda_bf16.h>
#include <math.h>
#include <stdint.h>

// ---------------------------------------------------------------------------
// Problem constants
// ---------------------------------------------------------------------------
#define N_MP 2
#define B_SZ 1024
#define S_FAN 10
#define D_DIM 512
#define E_DIM 64
#define ATT_DIM 128
#define N_CLASSES 8
#define N_NODES 4096

#define N1_ROWS (B_SZ)            // 1024
#define N2_ROWS (B_SZ * S_FAN)    // 10240

// ---------------------------------------------------------------------------
// Float scratch arena
// ---------------------------------------------------------------------------
#define OFF_E0   0LL
#define SZ_E0    (2LL*10240*64)
#define OFF_G0   (OFF_E0 + SZ_E0)
#define SZ_G0    (2LL*1024*10)
#define OFF_G1   (OFF_G0 + SZ_G0)
#define SZ_G1    (2LL*10240*10)
#define OFF_G2   (OFF_G1 + SZ_G1)
#define SZ_G2    (2LL*1024*10)
#define OFF_H0   (OFF_G2 + SZ_G2)
#define SZ_H0    (2LL*1024*512)
#define OFF_H1   (OFF_H0 + SZ_H0)
#define SZ_H1    (2LL*10240*512)
#define OFF_NE0  (OFF_H1 + SZ_H1)
#define SZ_NE0   (2LL*10240*64)
#define OFF_OUT  (OFF_NE0 + SZ_NE0)
#define SZ_OUT   (2LL*1024*512)
#define OFF_ATT  (OFF_OUT + SZ_OUT)
#define SZ_ATT   (2048LL)
#define FARENA_TOTAL (OFF_ATT + SZ_ATT)

__device__ float g_scratch[FARENA_TOTAL];

// ---------------------------------------------------------------------------
// bf16 scratch arena (hi/lo split operand planes)
// ---------------------------------------------------------------------------
#define BOFF_X0HI  0LL
#define BSZ_X0     (2LL*1024*1024)
#define BOFF_X0LO  (BOFF_X0HI + BSZ_X0)
#define BOFF_X1HI  (BOFF_X0LO + BSZ_X0)
#define BSZ_X1     (2LL*10240*1024)
#define BOFF_X1LO  (BOFF_X1HI + BSZ_X1)
#define BOFF_X2HI  (BOFF_X1LO + BSZ_X1)
#define BOFF_X2LO  (BOFF_X2HI + BSZ_X0)
#define BOFF_EINHI (BOFF_X2LO + BSZ_X0)
#define BSZ_EIN    (2LL*10240*1088)
#define BOFF_EINLO (BOFF_EINHI + BSZ_EIN)
#define BOFF_WTAHI (BOFF_EINLO + BSZ_EIN)
#define BSZ_WTA    (4LL*512*1024)
#define BOFF_WTALO (BOFF_WTAHI + BSZ_WTA)
#define BOFF_WTEHI (BOFF_WTALO + BSZ_WTA)
#define BSZ_WTE    (4LL*64*1088)
#define BOFF_WTELO (BOFF_WTEHI + BSZ_WTE)
#define BARENA_TOTAL (BOFF_WTELO + BSZ_WTE)

__device__ __nv_bfloat16 g_bscratch[BARENA_TOTAL];

// ---------------------------------------------------------------------------
// helpers
// ---------------------------------------------------------------------------
__device__ __forceinline__ uint32_t smem_u32(const void* p) {
    uint32_t a;
    asm("{ .reg .u64 t; cvta.to.shared.u64 t, %1; cvt.u32.u64 %0, t; }"
        : "=r"(a) : "l"(p));
    return a;
}

#define CP_ASYNC16(dst, src) \
    asm volatile("cp.async.cg.shared.global [%0], [%1], 16;" :: "r"(dst), "l"(src))
#define CP_COMMIT() asm volatile("cp.async.commit_group;")
#define CP_WAIT(n)  asm volatile("cp.async.wait_group %0;" :: "n"(n))

#define LDSM4(r, addr) \
    asm volatile("ldmatrix.sync.aligned.m8n8.x4.shared.b16 {%0,%1,%2,%3}, [%4];" \
        : "=r"((r)[0]), "=r"((r)[1]), "=r"((r)[2]), "=r"((r)[3]) : "r"(addr))
#define LDSM2(r, addr) \
    asm volatile("ldmatrix.sync.aligned.m8n8.x2.shared.b16 {%0,%1}, [%2];" \
        : "=r"((r)[0]), "=r"((r)[1]) : "r"(addr))

#define MMA_BF16(d, a, b) \
    asm volatile( \
        "mma.sync.aligned.m16n8k16.row.col.f32.bf16.bf16.f32 " \
        "{%0,%1,%2,%3}, {%4,%5,%6,%7}, {%8,%9}, {%0,%1,%2,%3};" \
        : "+f"((d)[0]), "+f"((d)[1]), "+f"((d)[2]), "+f"((d)[3]) \
        : "r"((a)[0]), "r"((a)[1]), "r"((a)[2]), "r"((a)[3]), \
          "r"((b)[0]), "r"((b)[1]))

__device__ __forceinline__ uint32_t pack2(float a, float b) {
    __nv_bfloat162 h = __floats2bfloat162_rn(a, b);
    return *(uint32_t*)&h;
}

__device__ __forceinline__ void split4(float4 v, float* h, float* l) {
    h[0] = __bfloat162float(__float2bfloat16_rn(v.x)); l[0] = v.x - h[0];
    h[1] = __bfloat162float(__float2bfloat16_rn(v.y)); l[1] = v.y - h[1];
    h[2] = __bfloat162float(__float2bfloat16_rn(v.z)); l[2] = v.z - h[2];
    h[3] = __bfloat162float(__float2bfloat16_rn(v.w)); l[3] = v.w - h[3];
}

// ---------------------------------------------------------------------------
// Weight transpose + bf16 hi/lo split: W[slice][K][N] -> Wt[slice][N][K]
// grid (K/32, N/32, n_slices), block (32, 8)
// ---------------------------------------------------------------------------
__global__ void transpose_split_kernel(
    const float* __restrict__ W, long long w_slice,
    __nv_bfloat16* __restrict__ Whi, __nv_bfloat16* __restrict__ Wlo,
    long long wt_slice, int K, int N)
{
    __shared__ float t[32][33];
    int sl = blockIdx.z;
    const float* Wp = W + (long long)sl * w_slice;
    int k0 = blockIdx.x * 32, n0 = blockIdx.y * 32;
    for (int r = threadIdx.y; r < 32; r += 8)
        t[r][threadIdx.x] = Wp[(long long)(k0 + r) * N + n0 + threadIdx.x];
    __syncthreads();
    __nv_bfloat16* ho = Whi + (long long)sl * wt_slice;
    __nv_bfloat16* lo = Wlo + (long long)sl * wt_slice;
    for (int r = threadIdx.y; r < 32; r += 8) {
        float v = t[threadIdx.x][r];                 // W[k0+tx][n0+r]
        float h = __bfloat162float(__float2bfloat16_rn(v));
        long long o = (long long)(n0 + r) * K + k0 + threadIdx.x;
        ho[o] = __float2bfloat16_rn(h);
        lo[o] = __float2bfloat16_rn(v - h);
    }
}

// ---------------------------------------------------------------------------
// bf16 3-pass GEMM, fused bias + ReLU.
// C[M,N_total] = relu( (Ahi+Alo)[M,K] @ (Bhi+Blo)[N,K]^T + bias )
// BM=128, BK=32; 256 threads = 8 warps (2 m x 4 n); cp.async double buffer.
// ---------------------------------------------------------------------------
template<int BN>
__global__ __launch_bounds__(256)
void bf16_gemm_bias_relu(
    const __nv_bfloat16* __restrict__ Ahi, const __nv_bfloat16* __restrict__ Alo,
    long long A_mp,
    const __nv_bfloat16* __restrict__ Bhi, const __nv_bfloat16* __restrict__ Blo,
    long long B_mp,
    const float* __restrict__ bias, long long bias_mp,
    float* __restrict__ C, long long C_mp,
    int K, int N_total)
{
    constexpr int BM = 128, BK = 32;
    constexpr int LDS = 40;                      // bf16 elems per smem row (80B, conflict-free)
    constexpr int A_MAT = BM * LDS;              // bf16 elems
    constexpr int B_MAT = BN * LDS;
    constexpr int STAGE = 2 * A_MAT + 2 * B_MAT; // bf16 elems per stage
    constexpr int MT = 4;                        // 4 m-tiles of 16 (warp m span 64)
    constexpr int NT = BN / 32;                  // n-tiles of 8 (warp n span BN/4)
    // byte offsets within a stage
    constexpr uint32_t OFF_ALO = A_MAT * 2;
    constexpr uint32_t OFF_BHI = 2 * A_MAT * 2;
    constexpr uint32_t OFF_BLO = OFF_BHI + B_MAT * 2;

    extern __shared__ __nv_bfloat16 smem[];
    uint32_t sbase0 = smem_u32(smem);

    int tid  = threadIdx.x;
    int wid  = tid >> 5;
    int lane = tid & 31;
    int wm   = wid >> 2;          // 0..1
    int wn   = wid & 3;           // 0..3
    int mp   = blockIdx.z;

    const __nv_bfloat16* Ahp = Ahi + (long long)mp * A_mp + (long long)blockIdx.y * BM * K;
    const __nv_bfloat16* Alp = Alo + (long long)mp * A_mp + (long long)blockIdx.y * BM * K;
    const __nv_bfloat16* Bhp = Bhi + (long long)mp * B_mp + (long long)blockIdx.x * BN * K;
    const __nv_bfloat16* Blp = Blo + (long long)mp * B_mp + (long long)blockIdx.x * BN * K;

    const int NKB = K / BK;

    auto issue = [&](int kb, int s) {
        int k0 = kb * BK;
        uint32_t sb = sbase0 + (uint32_t)s * STAGE * 2u;
#pragma unroll
        for (int i = 0; i < (BM * 4) / 256; i++) {      // A: 512 chunks / 256 thr
            int c = tid + i * 256;
            int row = c >> 2, ch = c & 3;
            long long g = (long long)row * K + k0 + ch * 8;
            uint32_t d = sb + (uint32_t)(row * 80 + ch * 16);
            CP_ASYNC16(d, Ahp + g);
            CP_ASYNC16(d + OFF_ALO, Alp + g);
        }
#pragma unroll
        for (int i = 0; i < (BN * 4) / 256; i++) {      // B chunks
            int c = tid + i * 256;
            int row = c >> 2, ch = c & 3;
            long long g = (long long)row * K + k0 + ch * 8;
            uint32_t d = sb + OFF_BHI + (uint32_t)(row * 80 + ch * 16);
            CP_ASYNC16(d, Bhp + g);
            CP_ASYNC16(d + (uint32_t)(B_MAT * 2), Blp + g);
        }
        CP_COMMIT();
    };

    float acc[MT][NT][4];
#pragma unroll
    for (int i = 0; i < MT; i++)
#pragma unroll
        for (int j = 0; j < NT; j++)
#pragma unroll
            for (int q = 0; q < 4; q++) acc[i][j][q] = 0.f;

    issue(0, 0);

    for (int kb = 0; kb < NKB; kb++) {
        int s = kb & 1;
        if (kb + 1 < NKB) { issue(kb + 1, s ^ 1); CP_WAIT(1); }
        else              { CP_WAIT(0); }
        __syncthreads();

        uint32_t sA = sbase0 + (uint32_t)s * STAGE * 2u;
#pragma unroll
        for (int ks = 0; ks < 2; ks++) {
            uint32_t a_hi[MT][4], a_lo[MT][4];
#pragma unroll
            for (int mi = 0; mi < MT; mi++) {
                int r = wm * 64 + mi * 16 + (lane & 15);
                uint32_t ad = sA + (uint32_t)(r * 80 + ks * 32 + ((lane >> 4) << 4));
                LDSM4(a_hi[mi], ad);
                LDSM4(a_lo[mi], ad + OFF_ALO);
            }
            uint32_t b_hi[NT][2], b_lo[NT][2];
#pragma unroll
            for (int ni = 0; ni < NT; ni++) {
                int r = wn * (BN / 4) + ni * 8 + (lane & 7);
                uint32_t bd = sA + OFF_BHI +
                              (uint32_t)(r * 80 + ks * 32 + (((lane >> 3) & 1) << 4));
                LDSM2(b_hi[ni], bd);
                LDSM2(b_lo[ni], bd + (uint32_t)(B_MAT * 2));
            }
#pragma unroll
            for (int mi = 0; mi < MT; mi++)
#pragma unroll
                for (int ni = 0; ni < NT; ni++) {
                    MMA_BF16(acc[mi][ni], a_hi[mi], b_hi[ni]);
                    MMA_BF16(acc[mi][ni], a_hi[mi], b_lo[ni]);
                    MMA_BF16(acc[mi][ni], a_lo[mi], b_hi[ni]);
                }
        }
        __syncthreads();
    }

    // epilogue
    const float* bp = bias + (long long)mp * bias_mp;
    float* Cp = C + (long long)mp * C_mp;
    int mrow0 = blockIdx.y * BM + wm * 64;
#pragma unroll
    for (int mi = 0; mi < MT; mi++) {
#pragma unroll
        for (int ni = 0; ni < NT; ni++) {
            int col = blockIdx.x * BN + wn * (BN / 4) + ni * 8 + (lane & 3) * 2;
            float b0 = __ldg(bp + col), b1 = __ldg(bp + col + 1);
            int r0 = mrow0 + mi * 16 + (lane >> 2);
            Cp[(long long)r0 * N_total + col]     = fmaxf(acc[mi][ni][0] + b0, 0.f);
            Cp[(long long)r0 * N_total + col + 1] = fmaxf(acc[mi][ni][1] + b1, 0.f);
            Cp[(long long)(r0 + 8) * N_total + col]     = fmaxf(acc[mi][ni][2] + b0, 0.f);
            Cp[(long long)(r0 + 8) * N_total + col + 1] = fmaxf(acc[mi][ni][3] + b1, 0.f);
        }
    }
}

// ---------------------------------------------------------------------------
// Edge gating: one warp per row (scores = edge·v_gate, softmax over S)
// ---------------------------------------------------------------------------
__global__ void edge_gate_kernel(
    const int* __restrict__ src_ids, long long src_mp,
    const int* __restrict__ nb_ids,  long long nb_mp,
    const int* __restrict__ adjs,
    const float* __restrict__ edge_feat, long long ef_mp,
    const float* __restrict__ vg, long long vg_mp,
    float* __restrict__ gate_out, long long gate_mp,
    float* __restrict__ e_out, long long e_mp,
    int n_rows)
{
    int mp   = blockIdx.y;
    int warp = threadIdx.x >> 5;
    int lane = threadIdx.x & 31;
    int row  = blockIdx.x * (blockDim.x >> 5) + warp;
    if (row >= n_rows) return;

    const float* vgp = vg + (long long)mp * vg_mp;
    float v0 = vgp[lane], v1 = vgp[lane + 32];
    const float* ef = edge_feat + (long long)mp * ef_mp;

    int srcn = 0;
    if (adjs) srcn = src_ids[(long long)mp * src_mp + row];

    float scores[S_FAN];
#pragma unroll
    for (int s = 0; s < S_FAN; s++) {
        int eid;
        if (adjs) {
            int nb = nb_ids[(long long)mp * nb_mp + (long long)row * S_FAN + s];
            eid = adjs[(long long)srcn * N_NODES + nb];
        } else {
            eid = row * S_FAN + s;
        }
        const float* er = ef + (long long)eid * E_DIM;
        float e0 = er[lane], e1 = er[lane + 32];
        if (e_out) {
            float* eo = e_out + (long long)mp * e_mp + ((long long)row * S_FAN + s) * E_DIM;
            eo[lane] = e0; eo[lane + 32] = e1;
        }
        float p = e0 * v0 + e1 * v1;
#pragma unroll
        for (int off = 16; off; off >>= 1)
            p += __shfl_xor_sync(0xffffffffu, p, off);
        scores[s] = p;
    }
    float m = scores[0];
#pragma unroll
    for (int s = 1; s < S_FAN; s++) m = fmaxf(m, scores[s]);
    float sum = 0.f;
#pragma unroll
    for (int s = 0; s < S_FAN; s++) { scores[s] = expf(scores[s] - m); sum += scores[s]; }
    float inv = 1.f / sum;
    float* go = gate_out + (long long)mp * gate_mp + (long long)row * S_FAN;
#pragma unroll
    for (int s = 0; s < S_FAN; s++)
        if (lane == s) go[s] = scores[s] * inv;
}

// ---------------------------------------------------------------------------
// Gather a 512-col fp32 row -> bf16 hi/lo planes (identity when ids==null)
// ---------------------------------------------------------------------------
__global__ void gather_split_kernel(
    const int* __restrict__ ids, long long ids_mp,
    const float* __restrict__ src, long long src_mp, int src_stride,
    __nv_bfloat16* __restrict__ Ohi, __nv_bfloat16* __restrict__ Olo,
    long long o_mp, int ldo, int col_off)
{
    int mp = blockIdx.y, row = blockIdx.x;
    int r = ids ? ids[(long long)mp * ids_mp + row] : row;
    const float4* s4 = (const float4*)(src + (long long)mp * src_mp + (long long)r * src_stride);
    float4 v = s4[threadIdx.x];
    float h[4], l[4];
    split4(v, h, l);
    long long base = (long long)mp * o_mp + (long long)row * ldo + col_off + threadIdx.x * 4;
    *(uint32_t*)(Ohi + base)     = pack2(h[0], h[1]);
    *(uint32_t*)(Ohi + base + 2) = pack2(h[2], h[3]);
    *(uint32_t*)(Olo + base)     = pack2(l[0], l[1]);
    *(uint32_t*)(Olo + base + 2) = pack2(l[2], l[3]);
}

// ---------------------------------------------------------------------------
// Gate-weighted sum over S neighbors -> bf16 hi/lo planes
// ---------------------------------------------------------------------------
__global__ void weighted_gather_split_kernel(
    const int* __restrict__ nb, long long nb_mp,
    const float* __restrict__ gate, long long gate_mp,
    const float* __restrict__ src, long long src_mp,
    __nv_bfloat16* __restrict__ Ohi, __nv_bfloat16* __restrict__ Olo,
    long long o_mp, int ldo, int col_off)
{
    int mp = blockIdx.y, row = blockIdx.x;
    int t = threadIdx.x;
    const float* srcp = src + (long long)mp * src_mp;
    const float* gp = gate + (long long)mp * gate_mp + (long long)row * S_FAN;
    float4 acc = make_float4(0.f, 0.f, 0.f, 0.f);
#pragma unroll
    for (int s = 0; s < S_FAN; s++) {
        float w = gp[s];
        int idx = nb ? nb[(long long)mp * nb_mp + (long long)row * S_FAN + s]
                     : row * S_FAN + s;
        float4 v = ((const float4*)(srcp + (long long)idx * D_DIM))[t];
        acc.x = fmaf(w, v.x, acc.x);
        acc.y = fmaf(w, v.y, acc.y);
        acc.z = fmaf(w, v.z, acc.z);
        acc.w = fmaf(w, v.w, acc.w);
    }
    float h[4], l[4];
    split4(acc, h, l);
    long long base = (long long)mp * o_mp + (long long)row * ldo + col_off + t * 4;
    *(uint32_t*)(Ohi + base)     = pack2(h[0], h[1]);
    *(uint32_t*)(Ohi + base + 2) = pack2(h[2], h[3]);
    *(uint32_t*)(Olo + base)     = pack2(l[0], l[1]);
    *(uint32_t*)(Olo + base + 2) = pack2(l[2], l[3]);
}

// ---------------------------------------------------------------------------
// EIN = [H0[i/10] | H1[i] | E0[i]] (1088 cols) -> bf16 hi/lo planes
// ---------------------------------------------------------------------------
__global__ void concat_ein_split_kernel(
    const float* __restrict__ H0, long long h0_mp,
    const float* __restrict__ H1, long long h1_mp,
    const float* __restrict__ E0, long long e0_mp,
    __nv_bfloat16* __restrict__ Ohi, __nv_bfloat16* __restrict__ Olo,
    long long o_mp)
{
    int mp = blockIdx.y, row = blockIdx.x;
    const float4* h0 = (const float4*)(H0 + (long long)mp * h0_mp + (long long)(row / S_FAN) * D_DIM);
    const float4* h1 = (const float4*)(H1 + (long long)mp * h1_mp + (long long)row * D_DIM);
    const float4* e0 = (const float4*)(E0 + (long long)mp * e0_mp + (long long)row * E_DIM);
    long long rbase = (long long)mp * o_mp + (long long)row * (2 * D_DIM + E_DIM);
    for (int i = threadIdx.x; i < (2 * D_DIM + E_DIM) / 4; i += blockDim.x) {
        float4 v;
        if (i < 128)      v = h0[i];
        else if (i < 256) v = h1[i - 128];
        else              v = e0[i - 256];
        float h[4], l[4];
        split4(v, h, l);
        long long base = rbase + i * 4;
        *(uint32_t*)(Ohi + base)     = pack2(h[0], h[1]);
        *(uint32_t*)(Ohi + base + 2) = pack2(h[2], h[3]);
        *(uint32_t*)(Olo + base)     = pack2(l[0], l[1]);
        *(uint32_t*)(Olo + base + 2) = pack2(l[2], l[3]);
    }
}

// ---------------------------------------------------------------------------
// Metapath attention + final FC
// ---------------------------------------------------------------------------
__global__ void att_kernel(const float* __restrict__ OUT,
                           const float* __restrict__ Wa,
                           const float* __restrict__ ba,
                           const float* __restrict__ va,
                           float* __restrict__ att)
{
    __shared__ float srow[D_DIM];
    __shared__ float red[4];
    int g = blockIdx.x;
    const float4* o = (const float4*)(OUT + (long long)g * D_DIM);
    ((float4*)srow)[threadIdx.x] = o[threadIdx.x];
    __syncthreads();
    int j = threadIdx.x;
    float acc = ba[j];
#pragma unroll 8
    for (int k = 0; k < D_DIM; k++)
        acc = fmaf(srow[k], Wa[k * ATT_DIM + j], acc);
    float p = tanhf(acc) * va[j];
#pragma unroll
    for (int off = 16; off; off >>= 1)
        p += __shfl_xor_sync(0xffffffffu, p, off);
    if ((threadIdx.x & 31) == 0) red[threadIdx.x >> 5] = p;
    __syncthreads();
    if (threadIdx.x == 0) att[g] = red[0] + red[1] + red[2] + red[3];
}

__global__ void final_kernel(const float* __restrict__ OUT,
                             const float* __restrict__ att,
                             const float* __restrict__ W_fc,
                             const float* __restrict__ b_fc,
                             float* __restrict__ out)
{
    __shared__ float agg[D_DIM];
    int b = blockIdx.x;
    float a0 = att[b], a1 = att[B_SZ + b];
    float m = fmaxf(a0, a1);
    float e0 = expf(a0 - m), e1 = expf(a1 - m);
    float inv = 1.f / (e0 + e1);
    float w0 = e0 * inv, w1 = e1 * inv;
    const float4* o0 = (const float4*)(OUT + (long long)b * D_DIM);
    const float4* o1 = (const float4*)(OUT + (long long)(B_SZ + b) * D_DIM);
    float4 v0 = o0[threadIdx.x], v1 = o1[threadIdx.x];
    float4 r;
    r.x = w0 * v0.x + w1 * v1.x;
    r.y = w0 * v0.y + w1 * v1.y;
    r.z = w0 * v0.z + w1 * v1.z;
    r.w = w0 * v0.w + w1 * v1.w;
    ((float4*)agg)[threadIdx.x] = r;
    __syncthreads();
    int warp = threadIdx.x >> 5;
    int lane = threadIdx.x & 31;
    for (int c = warp; c < N_CLASSES; c += 4) {
        float s = 0.f;
        for (int k = lane; k < D_DIM; k += 32)
            s = fmaf(agg[k], W_fc[k * N_CLASSES + c], s);
#pragma unroll
        for (int off = 16; off; off >>= 1)
            s += __shfl_xor_sync(0xffffffffu, s, off);
        if (lane == 0) out[b * N_CLASSES + c] = fmaxf(s + b_fc[c], 0.f);
    }
}

// ---------------------------------------------------------------------------
// Launch
// ---------------------------------------------------------------------------
extern "C" void kernel_launch(void* const* d_in, const int* in_sizes, int n_in,
                              void* d_out, int out_size)
{
    const int*   ids      = (const int*)d_in[0];
    const float* feats    = (const float*)d_in[1];
    const int*   adjs     = (const int*)d_in[2];
    const float* edge_emb = (const float*)d_in[3];
    const int*   n1       = (const int*)d_in[4];
    const int*   n2       = (const int*)d_in[5];
    const float* W_agg    = (const float*)d_in[6];
    const float* b_agg    = (const float*)d_in[7];
    const float* v_gate   = (const float*)d_in[8];
    const float* W_edge   = (const float*)d_in[9];
    const float* b_edge   = (const float*)d_in[10];
    const float* Wa       = (const float*)d_in[11];
    const float* ba       = (const float*)d_in[12];
    const float* va       = (const float*)d_in[13];
    const float* W_fc     = (const float*)d_in[14];
    const float* b_fc     = (const float*)d_in[15];
    float* out = (float*)d_out;

    float* S;
    cudaGetSymbolAddress((void**)&S, g_scratch);
    __nv_bfloat16* BS;
    cudaGetSymbolAddress((void**)&BS, g_bscratch);

    float* E0   = S + OFF_E0;
    float* G0   = S + OFF_G0;
    float* G1   = S + OFF_G1;
    float* G2   = S + OFF_G2;
    float* H0   = S + OFF_H0;
    float* H1   = S + OFF_H1;
    float* NE0  = S + OFF_NE0;
    float* OUTB = S + OFF_OUT;
    float* ATT  = S + OFF_ATT;

    __nv_bfloat16* X0HI  = BS + BOFF_X0HI;
    __nv_bfloat16* X0LO  = BS + BOFF_X0LO;
    __nv_bfloat16* X1HI  = BS + BOFF_X1HI;
    __nv_bfloat16* X1LO  = BS + BOFF_X1LO;
    __nv_bfloat16* X2HI  = BS + BOFF_X2HI;
    __nv_bfloat16* X2LO  = BS + BOFF_X2LO;
    __nv_bfloat16* EINHI = BS + BOFF_EINHI;
    __nv_bfloat16* EINLO = BS + BOFF_EINLO;
    __nv_bfloat16* WTAHI = BS + BOFF_WTAHI;
    __nv_bfloat16* WTALO = BS + BOFF_WTALO;
    __nv_bfloat16* WTEHI = BS + BOFF_WTEHI;
    __nv_bfloat16* WTELO = BS + BOFF_WTELO;

    const long long E0_MP  = 10240LL * 64;
    const long long G0_MP  = 1024LL * 10;
    const long long G1_MP  = 10240LL * 10;
    const long long G2_MP  = 1024LL * 10;
    const long long H0_MP  = 1024LL * 512;
    const long long H1_MP  = 10240LL * 512;
    const long long NE0_MP = 10240LL * 64;
    const long long OUT_MP = 1024LL * 512;
    const long long VG_MP  = 2LL * 64;
    const long long X0_MP  = 1024LL * 1024;
    const long long X1_MP  = 10240LL * 1024;
    const long long EIN_MP = 10240LL * 1088;

    const long long SLA = 512LL * 1024;   // one [N=512,K=1024] weight slice
    const long long SLE = 64LL * 1088;    // one [N=64,K=1088] weight slice

    // dynamic smem: 2 stages * (2*128*40 + 2*BN*40) bf16
    const int SMEM128 = 2 * (2 * 128 * 40 + 2 * 128 * 40) * 2;   // 81920 B
    const int SMEM64  = 2 * (2 * 128 * 40 + 2 * 64 * 40) * 2;    // 61440 B
    cudaFuncSetAttribute(bf16_gemm_bias_relu<128>,
                         cudaFuncAttributeMaxDynamicSharedMemorySize, SMEM128);
    cudaFuncSetAttribute(bf16_gemm_bias_relu<64>,
                         cudaFuncAttributeMaxDynamicSharedMemorySize, SMEM64);

    // 0) transpose + split weights
    transpose_split_kernel<<<dim3(1024 / 32, 512 / 32, 4), dim3(32, 8)>>>(
        W_agg, 1024LL * 512, WTAHI, WTALO, SLA, 1024, 512);
    transpose_split_kernel<<<dim3(1088 / 32, 64 / 32, 4), dim3(32, 8)>>>(
        W_edge, 1088LL * 64, WTEHI, WTELO, SLE, 1088, 64);

    // 1) hop-1 gating (+ gather E0)
    edge_gate_kernel<<<dim3(N1_ROWS / 4, N_MP), 128>>>(
        ids, 0, n1, (long long)N1_ROWS * S_FAN, adjs,
        edge_emb, 0, v_gate, VG_MP, G0, G0_MP, E0, E0_MP, N1_ROWS);
    // 2) hop-2 gating
    edge_gate_kernel<<<dim3(N2_ROWS / 4, N_MP), 128>>>(
        n1, (long long)N1_ROWS * S_FAN, n2, (long long)N2_ROWS * S_FAN, adjs,
        edge_emb, 0, v_gate, VG_MP, G1, G1_MP, nullptr, 0, N2_ROWS);

    // 3/4) X0 = [feats[ids] | gated sum feats[n1]]  (bf16 hi/lo)
    gather_split_kernel<<<dim3(N1_ROWS, N_MP), 128>>>(
        ids, 0, feats, 0, D_DIM, X0HI, X0LO, X0_MP, 2 * D_DIM, 0);
    weighted_gather_split_kernel<<<dim3(N1_ROWS, N_MP), 128>>>(
        n1, (long long)N1_ROWS * S_FAN, G0, G0_MP, feats, 0,
        X0HI, X0LO, X0_MP, 2 * D_DIM, D_DIM);
    // 5/6) X1 = [feats[n1] | gated sum feats[n2]]
    gather_split_kernel<<<dim3(N2_ROWS, N_MP), 128>>>(
        n1, (long long)N1_ROWS * S_FAN, feats, 0, D_DIM,
        X1HI, X1LO, X1_MP, 2 * D_DIM, 0);
    weighted_gather_split_kernel<<<dim3(N2_ROWS, N_MP), 128>>>(
        n2, (long long)N2_ROWS * S_FAN, G1, G1_MP, feats, 0,
        X1HI, X1LO, X1_MP, 2 * D_DIM, D_DIM);

    // 7) H0 = relu(X0 @ W_agg[mp,0] + b)   [1024,1024]x[1024,512]
    bf16_gemm_bias_relu<128><<<dim3(4, 8, N_MP), 256, SMEM128>>>(
        X0HI, X0LO, X0_MP, WTAHI, WTALO, 2 * SLA, b_agg, 2LL * 512,
        H0, H0_MP, 1024, 512);
    // 8) H1 = relu(X1 @ W_agg[mp,0] + b)   [10240,1024]x[1024,512]
    bf16_gemm_bias_relu<128><<<dim3(4, 80, N_MP), 256, SMEM128>>>(
        X1HI, X1LO, X1_MP, WTAHI, WTALO, 2 * SLA, b_agg, 2LL * 512,
        H1, H1_MP, 1024, 512);

    // 9) EIN = [H0 rep | H1 | E0]  (bf16 hi/lo)
    concat_ein_split_kernel<<<dim3(N2_ROWS, N_MP), 128>>>(
        H0, H0_MP, H1, H1_MP, E0, E0_MP, EINHI, EINLO, EIN_MP);
    // 10) NE0 = relu(EIN @ W_edge[mp,0] + b)  [10240,1088]x[1088,64]
    bf16_gemm_bias_relu<64><<<dim3(1, 80, N_MP), 256, SMEM64>>>(
        EINHI, EINLO, EIN_MP, WTEHI, WTELO, 2 * SLE, b_edge, 2LL * 64,
        NE0, NE0_MP, 1088, 64);

    // 11) layer-1 gating from NE0 (contiguous), v_gate[mp,1]
    edge_gate_kernel<<<dim3(N1_ROWS / 4, N_MP), 128>>>(
        nullptr, 0, nullptr, 0, nullptr,
        NE0, NE0_MP, v_gate + E_DIM, VG_MP, G2, G2_MP, nullptr, 0, N1_ROWS);

    // 12/13) X2 = [H0 | gated sum of H1]
    gather_split_kernel<<<dim3(N1_ROWS, N_MP), 128>>>(
        nullptr, 0, H0, H0_MP, D_DIM, X2HI, X2LO, X0_MP, 2 * D_DIM, 0);
    weighted_gather_split_kernel<<<dim3(N1_ROWS, N_MP), 128>>>(
        nullptr, 0, G2, G2_MP, H1, H1_MP, X2HI, X2LO, X0_MP, 2 * D_DIM, D_DIM);

    // 14) OUT = relu(X2 @ W_agg[mp,1] + b)
    bf16_gemm_bias_relu<128><<<dim3(4, 8, N_MP), 256, SMEM128>>>(
        X2HI, X2LO, X0_MP, WTAHI + SLA, WTALO + SLA, 2 * SLA,
        b_agg + 512, 2LL * 512, OUTB, OUT_MP, 1024, 512);

    // 15) metapath attention
    att_kernel<<<N_MP * B_SZ, ATT_DIM>>>(OUTB, Wa, ba, va, ATT);
    // 16) final
    final_kernel<<<B_SZ, 128>>>(OUTB, ATT, W_fc, b_fc, out);
}

// round 4
// speedup vs baseline: 3.3451x; 1.5975x over previous
#include <cuda_runtime.h>
#include <cuda_bf16.h>
#include <math.h>
#include <stdint.h>

// ---------------------------------------------------------------------------
// Problem constants
// ---------------------------------------------------------------------------
#define N_MP 2
#define B_SZ 1024
#define S_FAN 10
#define D_DIM 512
#define E_DIM 64
#define ATT_DIM 128
#define N_CLASSES 8
#define N_NODES 4096

#define N1_ROWS (B_SZ)            // 1024
#define N2_ROWS (B_SZ * S_FAN)    // 10240

// ---------------------------------------------------------------------------
// fp32 scratch arena
// ---------------------------------------------------------------------------
#define OFF_G0   0LL
#define SZ_G0    (2LL*1024*10)
#define OFF_G1   (OFF_G0 + SZ_G0)
#define SZ_G1    (2LL*10240*10)
#define OFF_G2   (OFF_G1 + SZ_G1)
#define SZ_G2    (2LL*1024*10)
#define OFF_Q    (OFF_G2 + SZ_G2)
#define SZ_Q     (2LL*4096*512)
#define OFF_P    (OFF_Q + SZ_Q)
#define SZ_P     (2LL*4096*512)
#define OFF_M1   (OFF_P + SZ_P)
#define SZ_M1    (2LL*10240*64)
#define OFF_R    (OFF_M1 + SZ_M1)
#define SZ_R     (2LL*1024*64)
#define OFF_TE   (OFF_R + SZ_R)
#define SZ_TE    (2LL*10240*64)
#define OFF_OUT  (OFF_TE + SZ_TE)
#define SZ_OUT   (2LL*1024*512)
#define OFF_ATT  (OFF_OUT + SZ_OUT)
#define SZ_ATT   (2048LL)
#define FARENA_TOTAL (OFF_ATT + SZ_ATT)

__device__ float g_scratch[FARENA_TOTAL];

// ---------------------------------------------------------------------------
// bf16 scratch arena (hi/lo operand planes)
// ---------------------------------------------------------------------------
#define BOFF_FHI   0LL
#define BSZ_F      (4096LL*512)
#define BOFF_FLO   (BOFF_FHI + BSZ_F)
#define BOFF_E0HI  (BOFF_FLO + BSZ_F)
#define BSZ_E0     (2LL*10240*64)
#define BOFF_E0LO  (BOFF_E0HI + BSZ_E0)
#define BOFF_H0HI  (BOFF_E0LO + BSZ_E0)
#define BSZ_H0     (2LL*1024*512)
#define BOFF_H0LO  (BOFF_H0HI + BSZ_H0)
#define BOFF_H1HI  (BOFF_H0LO + BSZ_H0)
#define BSZ_H1     (2LL*10240*512)
#define BOFF_H1LO  (BOFF_H1HI + BSZ_H1)
#define BOFF_X2HI  (BOFF_H1LO + BSZ_H1)
#define BSZ_X2     (2LL*1024*1024)
#define BOFF_X2LO  (BOFF_X2HI + BSZ_X2)
#define BOFF_WTAHI (BOFF_X2LO + BSZ_X2)
#define BSZ_WTA    (4LL*512*1024)
#define BOFF_WTALO (BOFF_WTAHI + BSZ_WTA)
#define BOFF_WTEHI (BOFF_WTALO + BSZ_WTA)
#define BSZ_WTE    (4LL*64*1088)
#define BOFF_WTELO (BOFF_WTEHI + BSZ_WTE)
#define BARENA_TOTAL (BOFF_WTELO + BSZ_WTE)

__device__ __nv_bfloat16 g_bscratch[BARENA_TOTAL];

// ---------------------------------------------------------------------------
// helpers
// ---------------------------------------------------------------------------
__device__ __forceinline__ uint32_t smem_u32(const void* p) {
    uint32_t a;
    asm("{ .reg .u64 t; cvta.to.shared.u64 t, %1; cvt.u32.u64 %0, t; }"
        : "=r"(a) : "l"(p));
    return a;
}

#define CP_ASYNC16(dst, src) \
    asm volatile("cp.async.cg.shared.global [%0], [%1], 16;" :: "r"(dst), "l"(src))
#define CP_COMMIT() asm volatile("cp.async.commit_group;")
#define CP_WAIT(n)  asm volatile("cp.async.wait_group %0;" :: "n"(n))

#define LDSM4(r, addr) \
    asm volatile("ldmatrix.sync.aligned.m8n8.x4.shared.b16 {%0,%1,%2,%3}, [%4];" \
        : "=r"((r)[0]), "=r"((r)[1]), "=r"((r)[2]), "=r"((r)[3]) : "r"(addr))
#define LDSM2(r, addr) \
    asm volatile("ldmatrix.sync.aligned.m8n8.x2.shared.b16 {%0,%1}, [%2];" \
        : "=r"((r)[0]), "=r"((r)[1]) : "r"(addr))

#define MMA_BF16(d, a, b) \
    asm volatile( \
        "mma.sync.aligned.m16n8k16.row.col.f32.bf16.bf16.f32 " \
        "{%0,%1,%2,%3}, {%4,%5,%6,%7}, {%8,%9}, {%0,%1,%2,%3};" \
        : "+f"((d)[0]), "+f"((d)[1]), "+f"((d)[2]), "+f"((d)[3]) \
        : "r"((a)[0]), "r"((a)[1]), "r"((a)[2]), "r"((a)[3]), \
          "r"((b)[0]), "r"((b)[1]))

__device__ __forceinline__ uint32_t pack2(float a, float b) {
    __nv_bfloat162 h = __floats2bfloat162_rn(a, b);
    return *(uint32_t*)&h;
}

__device__ __forceinline__ void split4(const float* v, float* h, float* l) {
#pragma unroll
    for (int i = 0; i < 4; i++) {
        h[i] = __bfloat162float(__float2bfloat16_rn(v[i]));
        l[i] = v[i] - h[i];
    }
}

__device__ __forceinline__ void store_split4(
    __nv_bfloat16* Ohi, __nv_bfloat16* Olo, long long base, const float* a)
{
    float h[4], l[4];
    split4(a, h, l);
    *(uint32_t*)(Ohi + base)     = pack2(h[0], h[1]);
    *(uint32_t*)(Ohi + base + 2) = pack2(h[2], h[3]);
    *(uint32_t*)(Olo + base)     = pack2(l[0], l[1]);
    *(uint32_t*)(Olo + base + 2) = pack2(l[2], l[3]);
}

// ---------------------------------------------------------------------------
// Weight transpose + bf16 hi/lo split: W[slice][K][N] -> Wt[slice][N][K]
// ---------------------------------------------------------------------------
__global__ void transpose_split_kernel(
    const float* __restrict__ W, long long w_slice,
    __nv_bfloat16* __restrict__ Whi, __nv_bfloat16* __restrict__ Wlo,
    long long wt_slice, int K, int N)
{
    __shared__ float t[32][33];
    int sl = blockIdx.z;
    const float* Wp = W + (long long)sl * w_slice;
    int k0 = blockIdx.x * 32, n0 = blockIdx.y * 32;
    for (int r = threadIdx.y; r < 32; r += 8)
        t[r][threadIdx.x] = Wp[(long long)(k0 + r) * N + n0 + threadIdx.x];
    __syncthreads();
    __nv_bfloat16* ho = Whi + (long long)sl * wt_slice;
    __nv_bfloat16* lo = Wlo + (long long)sl * wt_slice;
    for (int r = threadIdx.y; r < 32; r += 8) {
        float v = t[threadIdx.x][r];
        float h = __bfloat162float(__float2bfloat16_rn(v));
        long long o = (long long)(n0 + r) * K + k0 + threadIdx.x;
        ho[o] = __float2bfloat16_rn(h);
        lo[o] = __float2bfloat16_rn(v - h);
    }
}

// ---------------------------------------------------------------------------
// Split a dense fp32 matrix's rows into bf16 hi/lo planes (512 cols/row)
// ---------------------------------------------------------------------------
__global__ void split_rows_kernel(
    const float* __restrict__ src,
    __nv_bfloat16* __restrict__ Ohi, __nv_bfloat16* __restrict__ Olo)
{
    int row = blockIdx.x, t = threadIdx.x;
    float4 v = ((const float4*)(src + (long long)row * D_DIM))[t];
    float a[4] = {v.x, v.y, v.z, v.w};
    store_split4(Ohi, Olo, (long long)row * D_DIM + t * 4, a);
}

// ---------------------------------------------------------------------------
// General bf16 3-pass GEMM. C = [relu](A@B^T [+ bias])
// A: [M, K] hi/lo planes, row stride lda. B: [N, K] hi/lo, row stride ldb.
// bias == null -> no bias, no relu. BM=128, BK=32, 256 thr, double buffer.
// ---------------------------------------------------------------------------
template<int BN>
__global__ __launch_bounds__(256)
void bf16_gemm(
    const __nv_bfloat16* __restrict__ Ahi, const __nv_bfloat16* __restrict__ Alo,
    long long A_mp, int lda,
    const __nv_bfloat16* __restrict__ Bhi, const __nv_bfloat16* __restrict__ Blo,
    long long B_mp, int ldb,
    const float* __restrict__ bias, long long bias_mp,
    float* __restrict__ C, long long C_mp, int ldc,
    int K)
{
    constexpr int BM = 128, BK = 32;
    constexpr int LDS = 40;
    constexpr int A_MAT = BM * LDS;
    constexpr int B_MAT = BN * LDS;
    constexpr int STAGE = 2 * A_MAT + 2 * B_MAT;
    constexpr int MT = 4;
    constexpr int NT = BN / 32;
    constexpr uint32_t OFF_ALO = A_MAT * 2;
    constexpr uint32_t OFF_BHI = 2 * A_MAT * 2;

    extern __shared__ __nv_bfloat16 smem[];
    uint32_t sbase0 = smem_u32(smem);

    int tid  = threadIdx.x;
    int wid  = tid >> 5;
    int lane = tid & 31;
    int wm   = wid >> 2;
    int wn   = wid & 3;
    int mp   = blockIdx.z;

    const __nv_bfloat16* Ahp = Ahi + (long long)mp * A_mp + (long long)blockIdx.y * BM * lda;
    const __nv_bfloat16* Alp = Alo + (long long)mp * A_mp + (long long)blockIdx.y * BM * lda;
    const __nv_bfloat16* Bhp = Bhi + (long long)mp * B_mp + (long long)blockIdx.x * BN * ldb;
    const __nv_bfloat16* Blp = Blo + (long long)mp * B_mp + (long long)blockIdx.x * BN * ldb;

    const int NKB = K / BK;

    auto issue = [&](int kb, int s) {
        int k0 = kb * BK;
        uint32_t sb = sbase0 + (uint32_t)s * STAGE * 2u;
#pragma unroll
        for (int i = 0; i < (BM * 4) / 256; i++) {
            int c = tid + i * 256;
            int row = c >> 2, ch = c & 3;
            long long g = (long long)row * lda + k0 + ch * 8;
            uint32_t d = sb + (uint32_t)(row * 80 + ch * 16);
            CP_ASYNC16(d, Ahp + g);
            CP_ASYNC16(d + OFF_ALO, Alp + g);
        }
#pragma unroll
        for (int i = 0; i < (BN * 4) / 256; i++) {
            int c = tid + i * 256;
            int row = c >> 2, ch = c & 3;
            long long g = (long long)row * ldb + k0 + ch * 8;
            uint32_t d = sb + OFF_BHI + (uint32_t)(row * 80 + ch * 16);
            CP_ASYNC16(d, Bhp + g);
            CP_ASYNC16(d + (uint32_t)(B_MAT * 2), Blp + g);
        }
        CP_COMMIT();
    };

    float acc[MT][NT][4];
#pragma unroll
    for (int i = 0; i < MT; i++)
#pragma unroll
        for (int j = 0; j < NT; j++)
#pragma unroll
            for (int q = 0; q < 4; q++) acc[i][j][q] = 0.f;

    issue(0, 0);

    for (int kb = 0; kb < NKB; kb++) {
        int s = kb & 1;
        if (kb + 1 < NKB) { issue(kb + 1, s ^ 1); CP_WAIT(1); }
        else              { CP_WAIT(0); }
        __syncthreads();

        uint32_t sA = sbase0 + (uint32_t)s * STAGE * 2u;
#pragma unroll
        for (int ks = 0; ks < 2; ks++) {
            uint32_t a_hi[MT][4], a_lo[MT][4];
#pragma unroll
            for (int mi = 0; mi < MT; mi++) {
                int r = wm * 64 + mi * 16 + (lane & 15);
                uint32_t ad = sA + (uint32_t)(r * 80 + ks * 32 + ((lane >> 4) << 4));
                LDSM4(a_hi[mi], ad);
                LDSM4(a_lo[mi], ad + OFF_ALO);
            }
            uint32_t b_hi[NT][2], b_lo[NT][2];
#pragma unroll
            for (int ni = 0; ni < NT; ni++) {
                int r = wn * (BN / 4) + ni * 8 + (lane & 7);
                uint32_t bd = sA + OFF_BHI +
                              (uint32_t)(r * 80 + ks * 32 + (((lane >> 3) & 1) << 4));
                LDSM2(b_hi[ni], bd);
                LDSM2(b_lo[ni], bd + (uint32_t)(B_MAT * 2));
            }
#pragma unroll
            for (int mi = 0; mi < MT; mi++)
#pragma unroll
                for (int ni = 0; ni < NT; ni++) {
                    MMA_BF16(acc[mi][ni], a_hi[mi], b_hi[ni]);
                    MMA_BF16(acc[mi][ni], a_hi[mi], b_lo[ni]);
                    MMA_BF16(acc[mi][ni], a_lo[mi], b_hi[ni]);
                }
        }
        __syncthreads();
    }

    // epilogue
    float* Cp = C + (long long)mp * C_mp;
    const float* bp = bias ? bias + (long long)mp * bias_mp : nullptr;
    int mrow0 = blockIdx.y * BM + wm * 64;
#pragma unroll
    for (int mi = 0; mi < MT; mi++) {
#pragma unroll
        for (int ni = 0; ni < NT; ni++) {
            int col = blockIdx.x * BN + wn * (BN / 4) + ni * 8 + (lane & 3) * 2;
            int r0 = mrow0 + mi * 16 + (lane >> 2);
            float v0 = acc[mi][ni][0], v1 = acc[mi][ni][1];
            float v2 = acc[mi][ni][2], v3 = acc[mi][ni][3];
            if (bp) {
                float b0 = __ldg(bp + col), b1 = __ldg(bp + col + 1);
                v0 = fmaxf(v0 + b0, 0.f); v1 = fmaxf(v1 + b1, 0.f);
                v2 = fmaxf(v2 + b0, 0.f); v3 = fmaxf(v3 + b1, 0.f);
            }
            Cp[(long long)r0 * ldc + col]           = v0;
            Cp[(long long)r0 * ldc + col + 1]       = v1;
            Cp[(long long)(r0 + 8) * ldc + col]     = v2;
            Cp[(long long)(r0 + 8) * ldc + col + 1] = v3;
        }
    }
}

// ---------------------------------------------------------------------------
// Edge gating: one warp per row; scores = edge·v_gate, softmax over S.
// Optionally writes gathered edge rows as bf16 hi/lo planes.
// ---------------------------------------------------------------------------
__global__ void edge_gate_kernel(
    const int* __restrict__ src_ids, long long src_mp,
    const int* __restrict__ nb_ids,  long long nb_mp,
    const int* __restrict__ adjs,
    const float* __restrict__ edge_emb,
    const float* __restrict__ vg, long long vg_mp,
    float* __restrict__ gate_out, long long gate_mp,
    __nv_bfloat16* __restrict__ e_hi, __nv_bfloat16* __restrict__ e_lo,
    long long e_mp, int n_rows)
{
    int mp   = blockIdx.y;
    int warp = threadIdx.x >> 5;
    int lane = threadIdx.x & 31;
    int row  = blockIdx.x * (blockDim.x >> 5) + warp;
    if (row >= n_rows) return;

    const float* vgp = vg + (long long)mp * vg_mp;
    float v0 = vgp[lane], v1 = vgp[lane + 32];

    int srcn = src_ids[(long long)mp * src_mp + row];

    float scores[S_FAN];
#pragma unroll
    for (int s = 0; s < S_FAN; s++) {
        int nb = nb_ids[(long long)mp * nb_mp + (long long)row * S_FAN + s];
        int eid = adjs[(long long)srcn * N_NODES + nb];
        const float* er = edge_emb + (long long)eid * E_DIM;
        float e0 = er[lane], e1 = er[lane + 32];
        if (e_hi) {
            long long eo = (long long)mp * e_mp + ((long long)row * S_FAN + s) * E_DIM;
            __nv_bfloat16 h0 = __float2bfloat16_rn(e0);
            __nv_bfloat16 h1 = __float2bfloat16_rn(e1);
            e_hi[eo + lane]      = h0;
            e_hi[eo + lane + 32] = h1;
            e_lo[eo + lane]      = __float2bfloat16_rn(e0 - __bfloat162float(h0));
            e_lo[eo + lane + 32] = __float2bfloat16_rn(e1 - __bfloat162float(h1));
        }
        float p = e0 * v0 + e1 * v1;
#pragma unroll
        for (int off = 16; off; off >>= 1)
            p += __shfl_xor_sync(0xffffffffu, p, off);
        scores[s] = p;
    }
    float m = scores[0];
#pragma unroll
    for (int s = 1; s < S_FAN; s++) m = fmaxf(m, scores[s]);
    float sum = 0.f;
#pragma unroll
    for (int s = 0; s < S_FAN; s++) { scores[s] = expf(scores[s] - m); sum += scores[s]; }
    float inv = 1.f / sum;
    float* go = gate_out + (long long)mp * gate_mp + (long long)row * S_FAN;
#pragma unroll
    for (int s = 0; s < S_FAN; s++)
        if (lane == s) go[s] = scores[s] * inv;
}

// ---------------------------------------------------------------------------
// Combine: H[row] = relu(Q[sel[row]] + sum_s g[row,s] * P[nb[row,s]] + bias)
// writes bf16 hi/lo planes (512 cols). block=128, grid (rows, mp)
// ---------------------------------------------------------------------------
__global__ void combine_kernel(
    const float* __restrict__ Q, const float* __restrict__ P, long long qp_mp,
    const int* __restrict__ sel, long long sel_mp,
    const int* __restrict__ nb, long long nb_mp,
    const float* __restrict__ gate, long long gate_mp,
    const float* __restrict__ bias, long long bias_mp,
    __nv_bfloat16* __restrict__ Ohi, __nv_bfloat16* __restrict__ Olo,
    long long o_mp)
{
    int mp = blockIdx.y, row = blockIdx.x, t = threadIdx.x;
    const float* Qp = Q + (long long)mp * qp_mp;
    const float* Pp = P + (long long)mp * qp_mp;
    int sid = sel[(long long)mp * sel_mp + row];
    float4 q = ((const float4*)(Qp + (long long)sid * D_DIM))[t];
    float a[4] = {q.x, q.y, q.z, q.w};
    const float* gp = gate + (long long)mp * gate_mp + (long long)row * S_FAN;
    const int* nbp = nb + (long long)mp * nb_mp + (long long)row * S_FAN;
#pragma unroll
    for (int s = 0; s < S_FAN; s++) {
        float w = gp[s];
        int idx = nbp[s];
        float4 v = ((const float4*)(Pp + (long long)idx * D_DIM))[t];
        a[0] = fmaf(w, v.x, a[0]);
        a[1] = fmaf(w, v.y, a[1]);
        a[2] = fmaf(w, v.z, a[2]);
        a[3] = fmaf(w, v.w, a[3]);
    }
    float4 b = ((const float4*)(bias + (long long)mp * bias_mp))[t];
    a[0] = fmaxf(a[0] + b.x, 0.f);
    a[1] = fmaxf(a[1] + b.y, 0.f);
    a[2] = fmaxf(a[2] + b.z, 0.f);
    a[3] = fmaxf(a[3] + b.w, 0.f);
    store_split4(Ohi, Olo, (long long)mp * o_mp + (long long)row * D_DIM + t * 4, a);
}

// ---------------------------------------------------------------------------
// Layer-1 gate scores: NE[i] = relu(R[i/10] + M1[i] + TE[i] + b_edge);
// score = NE · v_gate; softmax over the 10 edges of each output row.
// one warp per output row r. grid (256, mp), block 128
// ---------------------------------------------------------------------------
__global__ void scores_kernel(
    const float* __restrict__ R, long long r_mp,
    const float* __restrict__ M1, long long m_mp,
    const float* __restrict__ TE, long long te_mp,
    const float* __restrict__ be, long long be_mp,
    const float* __restrict__ vg, long long vg_mp,
    float* __restrict__ G2, long long g_mp)
{
    int mp = blockIdx.y;
    int warp = threadIdx.x >> 5, lane = threadIdx.x & 31;
    int r = blockIdx.x * 4 + warp;

    const float* vgp = vg + (long long)mp * vg_mp;
    float v0 = vgp[lane], v1 = vgp[lane + 32];
    float b0 = be[(long long)mp * be_mp + lane];
    float b1 = be[(long long)mp * be_mp + lane + 32];
    float r0 = R[(long long)mp * r_mp + (long long)r * E_DIM + lane];
    float r1 = R[(long long)mp * r_mp + (long long)r * E_DIM + lane + 32];

    float sc[S_FAN];
#pragma unroll
    for (int s = 0; s < S_FAN; s++) {
        long long i = (long long)r * S_FAN + s;
        float a0 = r0 + M1[(long long)mp * m_mp + i * E_DIM + lane]
                      + TE[(long long)mp * te_mp + i * E_DIM + lane] + b0;
        float a1 = r1 + M1[(long long)mp * m_mp + i * E_DIM + lane + 32]
                      + TE[(long long)mp * te_mp + i * E_DIM + lane + 32] + b1;
        float p = fmaxf(a0, 0.f) * v0 + fmaxf(a1, 0.f) * v1;
#pragma unroll
        for (int off = 16; off; off >>= 1)
            p += __shfl_xor_sync(0xffffffffu, p, off);
        sc[s] = p;
    }
    float m = sc[0];
#pragma unroll
    for (int s = 1; s < S_FAN; s++) m = fmaxf(m, sc[s]);
    float sum = 0.f;
#pragma unroll
    for (int s = 0; s < S_FAN; s++) { sc[s] = expf(sc[s] - m); sum += sc[s]; }
    float inv = 1.f / sum;
    float* go = G2 + (long long)mp * g_mp + (long long)r * S_FAN;
#pragma unroll
    for (int s = 0; s < S_FAN; s++)
        if (lane == s) go[s] = sc[s] * inv;
}

// ---------------------------------------------------------------------------
// Build X2 planes: left 512 = copy of H0 planes, right 512 = gate-weighted sum
// of H1 rows (contiguous r*10+s). grid (1024, mp), block 128.
// ---------------------------------------------------------------------------
__global__ void build_x2_kernel(
    const __nv_bfloat16* __restrict__ H0hi, const __nv_bfloat16* __restrict__ H0lo,
    long long h0_mp,
    const __nv_bfloat16* __restrict__ H1hi, const __nv_bfloat16* __restrict__ H1lo,
    long long h1_mp,
    const float* __restrict__ G2, long long g_mp,
    __nv_bfloat16* __restrict__ Xhi, __nv_bfloat16* __restrict__ Xlo,
    long long x_mp)
{
    int mp = blockIdx.y, r = blockIdx.x, t = threadIdx.x;
    long long hb = (long long)mp * h0_mp + (long long)r * D_DIM + t * 4;
    long long xb = (long long)mp * x_mp + (long long)r * (2 * D_DIM) + t * 4;
    *(uint2*)(Xhi + xb) = *(const uint2*)(H0hi + hb);
    *(uint2*)(Xlo + xb) = *(const uint2*)(H0lo + hb);

    const float* gp = G2 + (long long)mp * g_mp + (long long)r * S_FAN;
    float a[4] = {0.f, 0.f, 0.f, 0.f};
#pragma unroll
    for (int s = 0; s < S_FAN; s++) {
        float w = gp[s];
        long long p = (long long)mp * h1_mp + ((long long)r * S_FAN + s) * D_DIM + t * 4;
        uint2 uh = *(const uint2*)(H1hi + p);
        uint2 ul = *(const uint2*)(H1lo + p);
        float2 h0 = __bfloat1622float2(*(__nv_bfloat162*)&uh.x);
        float2 h1 = __bfloat1622float2(*(__nv_bfloat162*)&uh.y);
        float2 l0 = __bfloat1622float2(*(__nv_bfloat162*)&ul.x);
        float2 l1 = __bfloat1622float2(*(__nv_bfloat162*)&ul.y);
        a[0] = fmaf(w, h0.x + l0.x, a[0]);
        a[1] = fmaf(w, h0.y + l0.y, a[1]);
        a[2] = fmaf(w, h1.x + l1.x, a[2]);
        a[3] = fmaf(w, h1.y + l1.y, a[3]);
    }
    store_split4(Xhi, Xlo, xb + D_DIM, a);
}

// ---------------------------------------------------------------------------
// Metapath attention + final FC
// ---------------------------------------------------------------------------
__global__ void att_kernel(const float* __restrict__ OUT,
                           const float* __restrict__ Wa,
                           const float* __restrict__ ba,
                           const float* __restrict__ va,
                           float* __restrict__ att)
{
    __shared__ float srow[D_DIM];
    __shared__ float red[4];
    int g = blockIdx.x;
    const float4* o = (const float4*)(OUT + (long long)g * D_DIM);
    ((float4*)srow)[threadIdx.x] = o[threadIdx.x];
    __syncthreads();
    int j = threadIdx.x;
    float acc = ba[j];
#pragma unroll 8
    for (int k = 0; k < D_DIM; k++)
        acc = fmaf(srow[k], Wa[k * ATT_DIM + j], acc);
    float p = tanhf(acc) * va[j];
#pragma unroll
    for (int off = 16; off; off >>= 1)
        p += __shfl_xor_sync(0xffffffffu, p, off);
    if ((threadIdx.x & 31) == 0) red[threadIdx.x >> 5] = p;
    __syncthreads();
    if (threadIdx.x == 0) att[g] = red[0] + red[1] + red[2] + red[3];
}

__global__ void final_kernel(const float* __restrict__ OUT,
                             const float* __restrict__ att,
                             const float* __restrict__ W_fc,
                             const float* __restrict__ b_fc,
                             float* __restrict__ out)
{
    __shared__ float agg[D_DIM];
    int b = blockIdx.x;
    float a0 = att[b], a1 = att[B_SZ + b];
    float m = fmaxf(a0, a1);
    float e0 = expf(a0 - m), e1 = expf(a1 - m);
    float inv = 1.f / (e0 + e1);
    float w0 = e0 * inv, w1 = e1 * inv;
    const float4* o0 = (const float4*)(OUT + (long long)b * D_DIM);
    const float4* o1 = (const float4*)(OUT + (long long)(B_SZ + b) * D_DIM);
    float4 v0 = o0[threadIdx.x], v1 = o1[threadIdx.x];
    float4 r;
    r.x = w0 * v0.x + w1 * v1.x;
    r.y = w0 * v0.y + w1 * v1.y;
    r.z = w0 * v0.z + w1 * v1.z;
    r.w = w0 * v0.w + w1 * v1.w;
    ((float4*)agg)[threadIdx.x] = r;
    __syncthreads();
    int warp = threadIdx.x >> 5;
    int lane = threadIdx.x & 31;
    for (int c = warp; c < N_CLASSES; c += 4) {
        float s = 0.f;
        for (int k = lane; k < D_DIM; k += 32)
            s = fmaf(agg[k], W_fc[k * N_CLASSES + c], s);
#pragma unroll
        for (int off = 16; off; off >>= 1)
            s += __shfl_xor_sync(0xffffffffu, s, off);
        if (lane == 0) out[b * N_CLASSES + c] = fmaxf(s + b_fc[c], 0.f);
    }
}

// ---------------------------------------------------------------------------
// Launch
// ---------------------------------------------------------------------------
extern "C" void kernel_launch(void* const* d_in, const int* in_sizes, int n_in,
                              void* d_out, int out_size)
{
    const int*   ids      = (const int*)d_in[0];
    const float* feats    = (const float*)d_in[1];
    const int*   adjs     = (const int*)d_in[2];
    const float* edge_emb = (const float*)d_in[3];
    const int*   n1       = (const int*)d_in[4];
    const int*   n2       = (const int*)d_in[5];
    const float* W_agg    = (const float*)d_in[6];
    const float* b_agg    = (const float*)d_in[7];
    const float* v_gate   = (const float*)d_in[8];
    const float* W_edge   = (const float*)d_in[9];
    const float* b_edge   = (const float*)d_in[10];
    const float* Wa       = (const float*)d_in[11];
    const float* ba       = (const float*)d_in[12];
    const float* va       = (const float*)d_in[13];
    const float* W_fc     = (const float*)d_in[14];
    const float* b_fc     = (const float*)d_in[15];
    float* out = (float*)d_out;

    float* S;
    cudaGetSymbolAddress((void**)&S, g_scratch);
    __nv_bfloat16* BS;
    cudaGetSymbolAddress((void**)&BS, g_bscratch);

    float* G0   = S + OFF_G0;
    float* G1   = S + OFF_G1;
    float* G2   = S + OFF_G2;
    float* Q    = S + OFF_Q;
    float* P    = S + OFF_P;
    float* M1   = S + OFF_M1;
    float* R    = S + OFF_R;
    float* TE   = S + OFF_TE;
    float* OUTB = S + OFF_OUT;
    float* ATT  = S + OFF_ATT;

    __nv_bfloat16* FHI  = BS + BOFF_FHI;
    __nv_bfloat16* FLO  = BS + BOFF_FLO;
    __nv_bfloat16* E0HI = BS + BOFF_E0HI;
    __nv_bfloat16* E0LO = BS + BOFF_E0LO;
    __nv_bfloat16* H0HI = BS + BOFF_H0HI;
    __nv_bfloat16* H0LO = BS + BOFF_H0LO;
    __nv_bfloat16* H1HI = BS + BOFF_H1HI;
    __nv_bfloat16* H1LO = BS + BOFF_H1LO;
    __nv_bfloat16* X2HI = BS + BOFF_X2HI;
    __nv_bfloat16* X2LO = BS + BOFF_X2LO;
    __nv_bfloat16* WTAHI = BS + BOFF_WTAHI;
    __nv_bfloat16* WTALO = BS + BOFF_WTALO;
    __nv_bfloat16* WTEHI = BS + BOFF_WTEHI;
    __nv_bfloat16* WTELO = BS + BOFF_WTELO;

    const long long G0_MP = 1024LL * 10;
    const long long G1_MP = 10240LL * 10;
    const long long G2_MP = 1024LL * 10;
    const long long QP_MP = 4096LL * 512;
    const long long M1_MP = 10240LL * 64;
    const long long R_MP  = 1024LL * 64;
    const long long TE_MP = 10240LL * 64;
    const long long E0_MP = 10240LL * 64;
    const long long H0_MP = 1024LL * 512;
    const long long H1_MP = 10240LL * 512;
    const long long X2_MP = 1024LL * 1024;
    const long long OUT_MP = 1024LL * 512;
    const long long VG_MP = 2LL * 64;
    const long long SLA = 512LL * 1024;   // [N=512,K=1024] weight slice
    const long long SLE = 64LL * 1088;    // [N=64,K=1088] weight slice

    const int SMEM128 = 2 * (2 * 128 * 40 + 2 * 128 * 40) * 2;   // 81920 B
    const int SMEM64  = 2 * (2 * 128 * 40 + 2 * 64 * 40) * 2;    // 61440 B
    cudaFuncSetAttribute(bf16_gemm<128>,
                         cudaFuncAttributeMaxDynamicSharedMemorySize, SMEM128);
    cudaFuncSetAttribute(bf16_gemm<64>,
                         cudaFuncAttributeMaxDynamicSharedMemorySize, SMEM64);

    // 0) weight prep
    transpose_split_kernel<<<dim3(32, 16, 4), dim3(32, 8)>>>(
        W_agg, 1024LL * 512, WTAHI, WTALO, SLA, 1024, 512);
    transpose_split_kernel<<<dim3(34, 2, 4), dim3(32, 8)>>>(
        W_edge, 1088LL * 64, WTEHI, WTELO, SLE, 1088, 64);
    // feats -> bf16 hi/lo planes
    split_rows_kernel<<<N_NODES, 128>>>(feats, FHI, FLO);

    // 1) hop-1 gating (+ E0 planes), 2) hop-2 gating
    edge_gate_kernel<<<dim3(N1_ROWS / 4, N_MP), 128>>>(
        ids, 0, n1, (long long)N1_ROWS * S_FAN, adjs, edge_emb,
        v_gate, VG_MP, G0, G0_MP, E0HI, E0LO, E0_MP, N1_ROWS);
    edge_gate_kernel<<<dim3(N2_ROWS / 4, N_MP), 128>>>(
        n1, (long long)N1_ROWS * S_FAN, n2, (long long)N2_ROWS * S_FAN, adjs,
        edge_emb, v_gate, VG_MP, G1, G1_MP, nullptr, nullptr, 0, N2_ROWS);

    // 3) Q = feats @ W_agg[mp,0][:512,:],  P = feats @ W_agg[mp,0][512:,:]
    bf16_gemm<128><<<dim3(4, 32, N_MP), 256, SMEM128>>>(
        FHI, FLO, 0, 512, WTAHI, WTALO, 2 * SLA, 1024,
        nullptr, 0, Q, QP_MP, 512, 512);
    bf16_gemm<128><<<dim3(4, 32, N_MP), 256, SMEM128>>>(
        FHI, FLO, 0, 512, WTAHI + 512, WTALO + 512, 2 * SLA, 1024,
        nullptr, 0, P, QP_MP, 512, 512);

    // 4) H1 = relu(Q[n1] + sum_s G1*P[n2] + b_agg[mp,0]); H0 likewise
    combine_kernel<<<dim3(N2_ROWS, N_MP), 128>>>(
        Q, P, QP_MP, n1, (long long)N1_ROWS * S_FAN,
        n2, (long long)N2_ROWS * S_FAN, G1, G1_MP,
        b_agg, 2LL * 512, H1HI, H1LO, H1_MP);
    combine_kernel<<<dim3(N1_ROWS, N_MP), 128>>>(
        Q, P, QP_MP, ids, 0,
        n1, (long long)N1_ROWS * S_FAN, G0, G0_MP,
        b_agg, 2LL * 512, H0HI, H0LO, H0_MP);

    // 5) edge-update partial GEMMs: M1 = H1@We[512:1024], R = H0@We[:512],
    //    TE = E0@We[1024:1088]   (We = W_edge[mp,0], transposed [64,1088])
    bf16_gemm<64><<<dim3(1, 80, N_MP), 256, SMEM64>>>(
        H1HI, H1LO, H1_MP, 512, WTEHI + 512, WTELO + 512, 2 * SLE, 1088,
        nullptr, 0, M1, M1_MP, 64, 512);
    bf16_gemm<64><<<dim3(1, 8, N_MP), 256, SMEM64>>>(
        H0HI, H0LO, H0_MP, 512, WTEHI, WTELO, 2 * SLE, 1088,
        nullptr, 0, R, R_MP, 64, 512);
    bf16_gemm<64><<<dim3(1, 80, N_MP), 256, SMEM64>>>(
        E0HI, E0LO, E0_MP, 64, WTEHI + 1024, WTELO + 1024, 2 * SLE, 1088,
        nullptr, 0, TE, TE_MP, 64, 64);

    // 6) layer-1 gate scores
    scores_kernel<<<dim3(N1_ROWS / 4, N_MP), 128>>>(
        R, R_MP, M1, M1_MP, TE, TE_MP, b_edge, 2LL * 64,
        v_gate + E_DIM, VG_MP, G2, G2_MP);

    // 7) X2 = [H0 | sum_s G2*H1]
    build_x2_kernel<<<dim3(N1_ROWS, N_MP), 128>>>(
        H0HI, H0LO, H0_MP, H1HI, H1LO, H1_MP, G2, G2_MP, X2HI, X2LO, X2_MP);

    // 8) OUT = relu(X2 @ W_agg[mp,1] + b_agg[mp,1])
    bf16_gemm<128><<<dim3(4, 8, N_MP), 256, SMEM128>>>(
        X2HI, X2LO, X2_MP, 1024, WTAHI + SLA, WTALO + SLA, 2 * SLA, 1024,
        b_agg + 512, 2LL * 512, OUTB, OUT_MP, 512, 1024);

    // 9) attention + final
    att_kernel<<<N_MP * B_SZ, ATT_DIM>>>(OUTB, Wa, ba, va, ATT);
    final_kernel<<<B_SZ, 128>>>(OUTB, ATT, W_fc, b_fc, out);
}